// round 12
// baseline (speedup 1.0000x reference)
#include <cuda_runtime.h>
#include <cstdint>

#define NN 50000
#define NE 800000

__device__ __align__(16) float g_sums[NN * 64];
__device__ __align__(16) float g_cnt[NN];
__device__ __align__(16) float g_P[NN * 128];   // P = src @ W1aL^T + b1a (fp32)

__global__ void zero_kernel() {
    int i = blockIdx.x * blockDim.x + threadIdx.x;
    float4 z = make_float4(0.f, 0.f, 0.f, 0.f);
    if (i < NN * 16) ((float4*)g_sums)[i] = z;
    if (i < NN / 4 + 1 && i * 4 + 3 < NN) ((float4*)g_cnt)[i] = z;
    if (i < 4) g_cnt[NN - 1 - i] = 0.f;
}

__device__ __forceinline__ float to_tf32(float x) {
    float y;
    asm("cvt.rna.tf32.f32 %0, %1;" : "=f"(y) : "f"(x));
    return y;
}

__device__ __forceinline__ void mma_tf32(float d[4], const uint32_t a[4], const uint32_t b[2]) {
    asm volatile(
        "mma.sync.aligned.m16n8k8.row.col.f32.tf32.tf32.f32 "
        "{%0,%1,%2,%3}, {%4,%5,%6,%7}, {%8,%9}, {%0,%1,%2,%3};"
        : "+f"(d[0]), "+f"(d[1]), "+f"(d[2]), "+f"(d[3])
        : "r"(a[0]), "r"(a[1]), "r"(a[2]), "r"(a[3]), "r"(b[0]), "r"(b[1]));
}

__device__ __forceinline__ void ldA_s(uint32_t a[4], const char* p, int stride) {
    a[0] = *(const uint32_t*)p;
    a[1] = *(const uint32_t*)(p + 8 * stride);
    a[2] = *(const uint32_t*)(p + 16);
    a[3] = *(const uint32_t*)(p + 8 * stride + 16);
}
__device__ __forceinline__ void ldB(uint32_t b[2], const char* p) {
    b[0] = *(const uint32_t*)p;
    b[1] = *(const uint32_t*)(p + 16);
}

#define REDV2(ptr, x0, x1) \
    asm volatile("red.global.add.v2.f32 [%0], {%1,%2};" :: "l"(ptr), "f"(x0), "f"(x1) : "memory")

__device__ __forceinline__ void cp_async16(void* dst_smem, const void* src_g) {
    uint32_t d;
    asm("{ .reg .u64 t; cvta.to.shared.u64 t, %1; cvt.u32.u64 %0, t; }" : "=r"(d) : "l"(dst_smem));
    asm volatile("cp.async.cg.shared.global [%0], [%1], 16;" :: "r"(d), "l"(src_g) : "memory");
}
#define CP_COMMIT() asm volatile("cp.async.commit_group;" ::: "memory")
#define CP_WAIT0()  asm volatile("cp.async.wait_group 0;" ::: "memory")
#define CP_WAIT1()  asm volatile("cp.async.wait_group 1;" ::: "memory")

// row widths: 68/132 floats per row (both %32==4: conflict-free frags)
#define W68  272
#define W132 528

// ============================ P kernel =======================================
#define PO_A 0
#define PO_W 17408
#define SMEM_P (PO_W + 34816)

__global__ __launch_bounds__(256, 2)
void p_kernel(const float* __restrict__ src, const float* __restrict__ W1a,
              const float* __restrict__ b1a)
{
    extern __shared__ char sm[];
    char* sA = sm + PO_A;
    char* sW = sm + PO_W;
    const int tid = threadIdx.x, lane = tid & 31, w = tid >> 5;
    const int p = w & 1, q = w >> 1;
    const int r4 = lane >> 2, cb = (lane & 3) * 4, c2 = (lane & 3) * 2;

    for (int idx = tid; idx < 128 * 32; idx += 256) {
        int r = idx >> 5, kp2 = idx & 31;
        float2 v = *(const float2*)(W1a + r * 128 + kp2 * 2);
        v.x = to_tf32(v.x); v.y = to_tf32(v.y);
        *(float2*)(sW + r * W68 + kp2 * 8) = v;
    }

    const int base = blockIdx.x * 64;
    for (int idx = tid; idx < 64 * 32; idx += 256) {
        int n = idx >> 5, kp2 = idx & 31;
        int gn = base + n;
        float2 v = make_float2(0.f, 0.f);
        if (gn < NN) v = *(const float2*)(src + (size_t)gn * 64 + kp2 * 2);
        v.x = to_tf32(v.x); v.y = to_tf32(v.y);
        *(float2*)(sA + n * W68 + kp2 * 8) = v;
    }
    __syncthreads();

    float acc[2][4][4];
    #pragma unroll
    for (int s = 0; s < 2; s++)
        #pragma unroll
        for (int j = 0; j < 4; j++)
            { acc[s][j][0]=0.f; acc[s][j][1]=0.f; acc[s][j][2]=0.f; acc[s][j][3]=0.f; }

    #pragma unroll
    for (int k0 = 0; k0 < 8; k0++) {
        int kb = k0 * 32 + cb;
        uint32_t a[2][4];
        ldA_s(a[0], sA + (p * 32 + r4) * W68 + kb, W68);
        ldA_s(a[1], sA + (p * 32 + 16 + r4) * W68 + kb, W68);
        #pragma unroll
        for (int j = 0; j < 4; j++) {
            uint32_t b[2];
            ldB(b, sW + (q * 32 + j * 8 + r4) * W68 + kb);
            mma_tf32(acc[0][j], a[0], b);
            mma_tf32(acc[1][j], a[1], b);
        }
    }

    #pragma unroll
    for (int s = 0; s < 2; s++) {
        #pragma unroll
        for (int rh = 0; rh < 2; rh++) {
            int gn = base + p * 32 + s * 16 + rh * 8 + r4;
            if (gn < NN) {
                #pragma unroll
                for (int j = 0; j < 4; j++) {
                    int c0 = q * 32 + j * 8 + c2;
                    float2 o;
                    o.x = acc[s][j][rh * 2]     + __ldg(b1a + c0);
                    o.y = acc[s][j][rh * 2 + 1] + __ldg(b1a + c0 + 1);
                    *(float2*)(g_P + (size_t)gn * 128 + c0) = o;
                }
            }
        }
    }
}

// ============================ EDGE KERNEL ====================================
// 64-edge tiles, 256 threads, 2 CTA/SM.  W1aR fragments persist in registers.
// h & W1b stored with PP column perm {0,4,2,6,1,5,3,7} -> GEMM2 frags via LDS.64.
#define EO_COL 0                      // int [2][64]
#define EO_ROW 512                    // int [2][64]
#define EO_B1B 1024                   // 64 f
#define EO_XH  1280
#define EO_WB  (EO_XH + 64 * W132)
#define EO_P   (EO_WB + 64 * W132)
#define SMEM_EDGE (EO_P + 64 * W132)  // 102656 B -> 2 CTAs/SM

__global__ __launch_bounds__(256, 2)
void edge_kernel(const int* __restrict__ eidx, const float* __restrict__ eattr,
                 const float* __restrict__ W1a, const float* __restrict__ W1b,
                 const float* __restrict__ b1b)
{
    extern __shared__ char sm[];
    int*   sCol = (int*)(sm + EO_COL);
    int*   sRow = (int*)(sm + EO_ROW);
    float* sb1b = (float*)(sm + EO_B1B);
    char* sXH = sm + EO_XH;
    char* sWb = sm + EO_WB;
    char* sP  = sm + EO_P;

    const int tid = threadIdx.x, lane = tid & 31, w = tid >> 5;
    const int p = w & 1, q = w >> 1;          // p: 32-row strip, q: 32-col group
    const int r4 = lane >> 2, cb = (lane & 3) * 4, c2 = (lane & 3) * 2;
    const int t3 = lane & 3;
    // PP perm: col c -> (c&~7) + PP[c&7], PP = {0,4,2,6,1,5,3,7}
    const int ppb = ((t3 & 1) * 16) | ((t3 & 2) * 4);      // frag pair byte off {0,16,8,24}
    const int ppe = ((t3 & 1) << 1) | ((t3 >> 1) & 1);     // pos of col c2 within group {0,2,1,3}

    // stage W1b (tf32) into smem, PP-permuted columns
    for (int idx = tid; idx < 64 * 64; idx += 256) {
        int r = idx >> 6, kp2 = idx & 63;
        float2 v = *(const float2*)(W1b + r * 128 + kp2 * 2);
        v.x = to_tf32(v.x); v.y = to_tf32(v.y);
        int c = kp2 * 2;                                    // even col
        int pc = (c & ~7) + (((c & 2) >> 1) | ((c & 4) >> 1) | ((c & 1) << 2));
        // pos(even c): PP[c&7] for even c&7 in {0,2,4,6} -> {0,2,1,3}
        // computed as ((c&2)>>1)|((c&4)>>1)... verify: c&7=0->0, 2->1|0=1? 
        // use direct table instead below
        (void)pc;
        int c7 = c & 7;
        int pos;
        if (c7 == 0) pos = 0; else if (c7 == 2) pos = 2; else if (c7 == 4) pos = 1; else pos = 3;
        float* dstf = (float*)(sWb + r * W132);
        dstf[(c & ~7) + pos]     = v.x;   // col c
        dstf[(c & ~7) + pos + 4] = v.y;   // col c+1 (PP[c+1] = PP[c]+4)
    }
    if (tid < 64) sb1b[tid] = b1b[tid];

    // W1aR (cols 64..127) fragments -> registers, once
    uint32_t bfrag[8][4][2];
    {
        int kc = lane & 3;
        #pragma unroll
        for (int k0 = 0; k0 < 8; k0++) {
            #pragma unroll
            for (int j = 0; j < 4; j++) {
                int n0 = q * 32 + j * 8 + r4;
                const float* wp = W1a + n0 * 128 + 64 + k0 * 8 + kc;
                bfrag[k0][j][0] = __float_as_uint(to_tf32(__ldg(wp)));
                bfrag[k0][j][1] = __float_as_uint(to_tf32(__ldg(wp + 4)));
            }
        }
    }

    const int* rowI = eidx;        // int32 (jax x64 disabled)
    const int* colI = eidx + NE;
    const int step = gridDim.x;
    const int ntiles = NE / 64;

    int t = blockIdx.x;
    if (tid < 64 && t < ntiles) {
        sRow[tid] = rowI[t * 64 + tid];
        sCol[tid] = colI[t * 64 + tid];
    }
    __syncthreads();

    int buf = 0;
    for (; t < ntiles; t += step) {
        const int base = t * 64;
        const int* curCol = sCol + buf * 64;
        const int* curRow = sRow + buf * 64;

        // ---- cp.async group 1: eattr tile (raw fp32, unpermuted) ----
        #pragma unroll
        for (int i = 0; i < 4; i++) {
            int idx = i * 256 + tid;
            int e = idx >> 4, o16 = (idx & 15) * 16;
            cp_async16(sXH + e * W132 + o16,
                       (const char*)(eattr + (size_t)(base + e) * 64) + o16);
        }
        CP_COMMIT();
        // ---- cp.async group 2: P[col[e]] rows ----
        #pragma unroll
        for (int i = 0; i < 8; i++) {
            int idx = i * 256 + tid;
            int e = idx >> 5, o16 = (idx & 31) * 16;
            cp_async16(sP + e * W132 + o16,
                       (const char*)(g_P + (size_t)curCol[e] * 128) + o16);
        }
        CP_COMMIT();

        // prefetch next tile's indices (overlaps GEMM1)
        int nr = 0, nc = 0;
        int tn = t + step;
        if (tid < 64 && tn < ntiles) {
            nr = rowI[tn * 64 + tid];
            nc = colI[tn * 64 + tid];
        }

        CP_WAIT1();
        __syncthreads();

        // ---- GEMM1: eattr @ W1aR^T (K=64; B in regs; A cvt post-LDS) ----
        float acc[2][4][4];
        #pragma unroll
        for (int s = 0; s < 2; s++)
            #pragma unroll
            for (int j = 0; j < 4; j++)
                { acc[s][j][0]=0.f; acc[s][j][1]=0.f; acc[s][j][2]=0.f; acc[s][j][3]=0.f; }

        #pragma unroll
        for (int k0 = 0; k0 < 8; k0++) {
            int kb = k0 * 32 + cb;
            uint32_t a[2][4];
            ldA_s(a[0], sXH + (p * 32 + r4) * W132 + kb, W132);
            ldA_s(a[1], sXH + (p * 32 + 16 + r4) * W132 + kb, W132);
            #pragma unroll
            for (int s = 0; s < 2; s++)
                #pragma unroll
                for (int u = 0; u < 4; u++)
                    a[s][u] = __float_as_uint(to_tf32(__uint_as_float(a[s][u])));
            #pragma unroll
            for (int j = 0; j < 4; j++) {
                mma_tf32(acc[0][j], a[0], bfrag[k0][j]);
                mma_tf32(acc[1][j], a[1], bfrag[k0][j]);
            }
        }
        CP_WAIT0();
        __syncthreads();

        // ---- epi1: h = relu(acc + sP) -> sXH, PP-permuted columns ----
        #pragma unroll
        for (int s = 0; s < 2; s++) {
            int r0 = p * 32 + s * 16 + r4;
            #pragma unroll
            for (int j = 0; j < 4; j++) {
                int c0 = q * 32 + j * 8 + c2;
                float2 pa = *(const float2*)(sP + r0 * W132 + c0 * 4);
                float2 pb = *(const float2*)(sP + (r0 + 8) * W132 + c0 * 4);
                float v0x = to_tf32(fmaxf(acc[s][j][0] + pa.x, 0.f));
                float v0y = to_tf32(fmaxf(acc[s][j][1] + pa.y, 0.f));
                float v1x = to_tf32(fmaxf(acc[s][j][2] + pb.x, 0.f));
                float v1y = to_tf32(fmaxf(acc[s][j][3] + pb.y, 0.f));
                int pos = q * 32 + j * 8 + ppe;     // PP pos of col c0 (even)
                float* d0 = (float*)(sXH + r0 * W132);
                float* d1 = (float*)(sXH + (r0 + 8) * W132);
                d0[pos]     = v0x;   // col c0
                d0[pos + 4] = v0y;   // col c0+1
                d1[pos]     = v1x;
                d1[pos + 4] = v1y;
            }
        }
        __syncthreads();

        // ---- GEMM2: h @ W1b^T (K=128, N=64), LDS.64 fragments ----
        float acc2[2][2][4];
        #pragma unroll
        for (int s = 0; s < 2; s++)
            #pragma unroll
            for (int j = 0; j < 2; j++)
                { acc2[s][j][0]=0.f; acc2[s][j][1]=0.f; acc2[s][j][2]=0.f; acc2[s][j][3]=0.f; }

        #pragma unroll
        for (int k0 = 0; k0 < 16; k0++) {
            int kb = k0 * 32 + ppb;
            uint2 lo0 = *(const uint2*)(sXH + (p * 32 + r4) * W132 + kb);
            uint2 hi0 = *(const uint2*)(sXH + (p * 32 + 8 + r4) * W132 + kb);
            uint2 lo1 = *(const uint2*)(sXH + (p * 32 + 16 + r4) * W132 + kb);
            uint2 hi1 = *(const uint2*)(sXH + (p * 32 + 24 + r4) * W132 + kb);
            uint32_t a0[4] = {lo0.x, hi0.x, lo0.y, hi0.y};
            uint32_t a1[4] = {lo1.x, hi1.x, lo1.y, hi1.y};
            #pragma unroll
            for (int j = 0; j < 2; j++) {
                uint2 bb = *(const uint2*)(sWb + (q * 16 + j * 8 + r4) * W132 + kb);
                uint32_t b[2] = {bb.x, bb.y};
                mma_tf32(acc2[0][j], a0, b);
                mma_tf32(acc2[1][j], a1, b);
            }
        }

        // ---- epi2: +b1b, scatter-add, count (fire-and-forget) ----
        #pragma unroll
        for (int s = 0; s < 2; s++) {
            #pragma unroll
            for (int rh = 0; rh < 2; rh++) {
                int e = p * 32 + s * 16 + rh * 8 + r4;
                int r = curRow[e];
                if (q == 0 && (lane & 3) == 0) atomicAdd(&g_cnt[r], 1.0f);
                float* dst = g_sums + (size_t)r * 64;
                #pragma unroll
                for (int j = 0; j < 2; j++) {
                    int c0 = q * 16 + j * 8 + c2;
                    REDV2(dst + c0,
                          acc2[s][j][rh * 2]     + sb1b[c0],
                          acc2[s][j][rh * 2 + 1] + sb1b[c0 + 1]);
                }
            }
        }

        if (tid < 64) {
            sRow[(buf ^ 1) * 64 + tid] = nr;
            sCol[(buf ^ 1) * 64 + tid] = nc;
        }
        buf ^= 1;
        __syncthreads();
    }
}

// ============================== NODE KERNEL ==================================
// 64-node tiles, 1024 threads (32 warps), 1 CTA/SM.  (proven)
#define XW 132
#define XB (XW * 4)
#define NO_A   1280
#define NO_H   (NO_A + 64 * XB)
#define NO_WA  (NO_H + 64 * XB)
#define NO_WB  (NO_WA + 128 * XB)
#define NO_WR  (NO_WB + 64 * XB)
#define SMEM_NODE (NO_WR + 64 * XB)

__device__ __forceinline__ void stage_w(const float* __restrict__ W, char* dst, int R,
                                        int swap, int nthr) {
    for (int idx = threadIdx.x; idx < R * 64; idx += nthr) {
        int r = idx >> 6, kp2 = idx & 63;
        float2 v = *(const float2*)(W + r * 128 + kp2 * 2);
        v.x = to_tf32(v.x); v.y = to_tf32(v.y);
        int kd = swap ? (kp2 ^ 32) : kp2;
        *(float2*)(dst + r * XB + kd * 8) = v;
    }
}

__global__ __launch_bounds__(1024, 1)
void node_kernel(const float* __restrict__ src,
                 const float* __restrict__ W2a, const float* __restrict__ b2a,
                 const float* __restrict__ W2b, const float* __restrict__ b2b,
                 const float* __restrict__ Wr,  const float* __restrict__ br,
                 float* __restrict__ out)
{
    extern __shared__ char sm[];
    float* sb2a = (float*)sm;
    float* sb2b = (float*)(sm + 512);
    float* sbr  = (float*)(sm + 768);
    float* sInv = (float*)(sm + 1024);
    char* sA  = sm + NO_A;
    char* sH  = sm + NO_H;
    char* sWa = sm + NO_WA;
    char* sWb = sm + NO_WB;
    char* sWr = sm + NO_WR;

    const int tid = threadIdx.x, lane = tid & 31, w = tid >> 5;
    stage_w(W2a, sWa, 128, 0, 1024);
    stage_w(W2b, sWb, 64, 0, 1024);
    stage_w(Wr,  sWr, 64, 1, 1024);   // k-halves swapped: A=[src|z] vs concat(z,src)
    if (tid < 128) sb2a[tid] = b2a[tid];
    if (tid < 64)  sb2b[tid] = b2b[tid];
    if (tid < 64)  sbr[tid]  = br[tid];

    const int p = w & 3, jj = w >> 2;
    const int r4 = lane >> 2, cb = (lane & 3) * 4, c2 = (lane & 3) * 2;
    const int m0 = p * 16;

    const int ntiles = (NN + 63) / 64;
    for (int t = blockIdx.x; t < ntiles; t += gridDim.x) {
        const int base = t * 64;
        __syncthreads();
        if (tid < 64) {
            int gn = base + tid;
            float c = (gn < NN) ? g_cnt[gn] : 1.0f;
            sInv[tid] = 1.0f / fmaxf(c, 1.0f);
        }
        __syncthreads();

        #pragma unroll
        for (int i = 0; i < 4; i++) {
            int idx = i * 1024 + tid;
            int n = idx >> 6, kp2 = idx & 63;
            int gn = base + n;
            float2 v = make_float2(0.f, 0.f);
            if (gn < NN) {
                if (kp2 < 32) v = *(const float2*)(src + (size_t)gn * 64 + kp2 * 2);
                else {
                    float2 s2 = *(const float2*)(g_sums + (size_t)gn * 64 + (kp2 - 32) * 2);
                    float iv = sInv[n];
                    v = make_float2(s2.x * iv, s2.y * iv);
                }
            }
            v.x = to_tf32(v.x); v.y = to_tf32(v.y);
            *(float2*)(sA + n * XB + kp2 * 8) = v;
        }
        __syncthreads();

        float acc[2][4];
        #pragma unroll
        for (int j = 0; j < 2; j++) { acc[j][0]=0.f; acc[j][1]=0.f; acc[j][2]=0.f; acc[j][3]=0.f; }
        #pragma unroll
        for (int k0 = 0; k0 < 16; k0++) {
            int kb = k0 * 32 + cb;
            uint32_t a[4];
            ldA_s(a, sA + (m0 + r4) * XB + kb, XB);
            #pragma unroll
            for (int j = 0; j < 2; j++) {
                uint32_t b[2];
                ldB(b, sWa + (jj * 16 + j * 8 + r4) * XB + kb);
                mma_tf32(acc[j], a, b);
            }
        }
        #pragma unroll
        for (int j = 0; j < 2; j++) {
            int c0 = jj * 16 + j * 8 + c2;
            float bx = sb2a[c0], by = sb2a[c0 + 1];
            float2 v0, v1;
            v0.x = to_tf32(fmaxf(acc[j][0] + bx, 0.f));
            v0.y = to_tf32(fmaxf(acc[j][1] + by, 0.f));
            v1.x = to_tf32(fmaxf(acc[j][2] + bx, 0.f));
            v1.y = to_tf32(fmaxf(acc[j][3] + by, 0.f));
            *(float2*)(sH + (m0 + r4) * XB + c0 * 4) = v0;
            *(float2*)(sH + (m0 + 8 + r4) * XB + c0 * 4) = v1;
        }
        __syncthreads();

        float acc2[4];
        acc2[0]=0.f; acc2[1]=0.f; acc2[2]=0.f; acc2[3]=0.f;
        #pragma unroll
        for (int k0 = 0; k0 < 16; k0++) {
            int kb = k0 * 32 + cb;
            uint32_t a[4];
            ldA_s(a, sH + (m0 + r4) * XB + kb, XB);
            uint32_t b[2];
            ldB(b, sWb + (jj * 8 + r4) * XB + kb);
            mma_tf32(acc2, a, b);
        }
        {
            int c0 = jj * 8 + c2;
            float bx = sb2b[c0], by = sb2b[c0 + 1];
            float2 v0, v1;
            v0.x = to_tf32(acc2[0] + bx);
            v0.y = to_tf32(acc2[1] + by);
            v1.x = to_tf32(acc2[2] + bx);
            v1.y = to_tf32(acc2[3] + by);
            *(float2*)(sA + (m0 + r4) * XB + (64 + c0) * 4) = v0;
            *(float2*)(sA + (m0 + 8 + r4) * XB + (64 + c0) * 4) = v1;
        }
        __syncthreads();

        float acc3[4];
        acc3[0]=0.f; acc3[1]=0.f; acc3[2]=0.f; acc3[3]=0.f;
        #pragma unroll
        for (int k0 = 0; k0 < 16; k0++) {
            int kb = k0 * 32 + cb;
            uint32_t a[4];
            ldA_s(a, sA + (m0 + r4) * XB + kb, XB);
            uint32_t b[2];
            ldB(b, sWr + (jj * 8 + r4) * XB + kb);
            mma_tf32(acc3, a, b);
        }
        #pragma unroll
        for (int rh = 0; rh < 2; rh++) {
            int gn = base + m0 + rh * 8 + r4;
            if (gn < NN) {
                int c0 = jj * 8 + c2;
                float2 o = make_float2(acc3[rh * 2] + sbr[c0],
                                       acc3[rh * 2 + 1] + sbr[c0 + 1]);
                *(float2*)(out + (size_t)gn * 64 + c0) = o;
            }
        }
    }
}

// ---------------------------------------------------------------------------
extern "C" void kernel_launch(void* const* d_in, const int* in_sizes, int n_in,
                              void* d_out, int out_size) {
    const float* src   = (const float*)d_in[0];
    const int*   eidx  = (const int*)d_in[1];
    const float* eattr = (const float*)d_in[2];
    const float* W1a = (const float*)d_in[5];
    const float* b1a = (const float*)d_in[6];
    const float* W1b = (const float*)d_in[7];
    const float* b1b = (const float*)d_in[8];
    const float* W2a = (const float*)d_in[9];
    const float* b2a = (const float*)d_in[10];
    const float* W2b = (const float*)d_in[11];
    const float* b2b = (const float*)d_in[12];
    const float* Wr  = (const float*)d_in[13];
    const float* br  = (const float*)d_in[14];
    float* out = (float*)d_out;

    cudaFuncSetAttribute(p_kernel,    cudaFuncAttributeMaxDynamicSharedMemorySize, SMEM_P);
    cudaFuncSetAttribute(edge_kernel, cudaFuncAttributeMaxDynamicSharedMemorySize, SMEM_EDGE);
    cudaFuncSetAttribute(node_kernel, cudaFuncAttributeMaxDynamicSharedMemorySize, SMEM_NODE);

    zero_kernel<<<(NN * 16 + 255) / 256, 256>>>();
    p_kernel<<<(NN + 63) / 64, 256, SMEM_P>>>(src, W1a, b1a);
    edge_kernel<<<296, 256, SMEM_EDGE>>>(eidx, eattr, W1a, W1b, b1b);
    node_kernel<<<148, 1024, SMEM_NODE>>>(src, W2a, b2a, W2b, b2b, Wr, br, out);
}

// round 13
// speedup vs baseline: 1.5657x; 1.5657x over previous
#include <cuda_runtime.h>
#include <cuda_fp16.h>
#include <cstdint>

#define NN 50000
#define NE 800000

__device__ __align__(16) float g_sums[NN * 64];
__device__ __align__(16) float g_cnt[NN];
__device__ __align__(16) float g_P[NN * 128];   // P = src @ W1aL^T + b1a (fp32)

__global__ void zero_kernel() {
    int i = blockIdx.x * blockDim.x + threadIdx.x;
    float4 z = make_float4(0.f, 0.f, 0.f, 0.f);
    if (i < NN * 16) ((float4*)g_sums)[i] = z;
    if (i < NN / 4 + 1 && i * 4 + 3 < NN) ((float4*)g_cnt)[i] = z;
    if (i < 4) g_cnt[NN - 1 - i] = 0.f;
}

__device__ __forceinline__ float to_tf32(float x) {
    float y;
    asm("cvt.rna.tf32.f32 %0, %1;" : "=f"(y) : "f"(x));
    return y;
}
__device__ __forceinline__ uint32_t f2h2(float x, float y) {
    __half2 h = __floats2half2_rn(x, y);
    return *reinterpret_cast<uint32_t*>(&h);
}

__device__ __forceinline__ void mma_tf32(float d[4], const uint32_t a[4], const uint32_t b[2]) {
    asm volatile(
        "mma.sync.aligned.m16n8k8.row.col.f32.tf32.tf32.f32 "
        "{%0,%1,%2,%3}, {%4,%5,%6,%7}, {%8,%9}, {%0,%1,%2,%3};"
        : "+f"(d[0]), "+f"(d[1]), "+f"(d[2]), "+f"(d[3])
        : "r"(a[0]), "r"(a[1]), "r"(a[2]), "r"(a[3]), "r"(b[0]), "r"(b[1]));
}
__device__ __forceinline__ void mma_f16(float d[4], const uint32_t a[4], const uint32_t b[2]) {
    asm volatile(
        "mma.sync.aligned.m16n8k16.row.col.f32.f16.f16.f32 "
        "{%0,%1,%2,%3}, {%4,%5,%6,%7}, {%8,%9}, {%0,%1,%2,%3};"
        : "+f"(d[0]), "+f"(d[1]), "+f"(d[2]), "+f"(d[3])
        : "r"(a[0]), "r"(a[1]), "r"(a[2]), "r"(a[3]), "r"(b[0]), "r"(b[1]));
}

// A fragment, row stride `stride` bytes (fp16: covers 16x16, tf32: 16x8)
__device__ __forceinline__ void ldA_s(uint32_t a[4], const char* p, int stride) {
    a[0] = *(const uint32_t*)p;
    a[1] = *(const uint32_t*)(p + 8 * stride);
    a[2] = *(const uint32_t*)(p + 16);
    a[3] = *(const uint32_t*)(p + 8 * stride + 16);
}
__device__ __forceinline__ void ldB(uint32_t b[2], const char* p) {
    b[0] = *(const uint32_t*)p;
    b[1] = *(const uint32_t*)(p + 16);
}

#define REDV2(ptr, x0, x1) \
    asm volatile("red.global.add.v2.f32 [%0], {%1,%2};" :: "l"(ptr), "f"(x0), "f"(x1) : "memory")

__device__ __forceinline__ void cp_async16(void* dst_smem, const void* src_g) {
    uint32_t d;
    asm("{ .reg .u64 t; cvta.to.shared.u64 t, %1; cvt.u32.u64 %0, t; }" : "=r"(d) : "l"(dst_smem));
    asm volatile("cp.async.cg.shared.global [%0], [%1], 16;" :: "r"(d), "l"(src_g) : "memory");
}
#define CP_COMMIT() asm volatile("cp.async.commit_group;" ::: "memory")
#define CP_WAIT0()  asm volatile("cp.async.wait_group 0;" ::: "memory")

#define W68  272     // tf32 rows: 68 floats
#define W132 528     // fp32 rows: 132 floats
#define HB   272     // fp16 rows: 136 halves = 272 bytes (conflict-free, proven R4)

// ============================ P kernel (tf32, unchanged) =====================
#define PO_A 0
#define PO_W 17408
#define SMEM_P (PO_W + 34816)

__global__ __launch_bounds__(256, 2)
void p_kernel(const float* __restrict__ src, const float* __restrict__ W1a,
              const float* __restrict__ b1a)
{
    extern __shared__ char sm[];
    char* sA = sm + PO_A;
    char* sW = sm + PO_W;
    const int tid = threadIdx.x, lane = tid & 31, w = tid >> 5;
    const int p = w & 1, q = w >> 1;
    const int r4 = lane >> 2, cb = (lane & 3) * 4, c2 = (lane & 3) * 2;

    for (int idx = tid; idx < 128 * 32; idx += 256) {
        int r = idx >> 5, kp2 = idx & 31;
        float2 v = *(const float2*)(W1a + r * 128 + kp2 * 2);
        v.x = to_tf32(v.x); v.y = to_tf32(v.y);
        *(float2*)(sW + r * W68 + kp2 * 8) = v;
    }

    const int base = blockIdx.x * 64;
    for (int idx = tid; idx < 64 * 32; idx += 256) {
        int n = idx >> 5, kp2 = idx & 31;
        int gn = base + n;
        float2 v = make_float2(0.f, 0.f);
        if (gn < NN) v = *(const float2*)(src + (size_t)gn * 64 + kp2 * 2);
        v.x = to_tf32(v.x); v.y = to_tf32(v.y);
        *(float2*)(sA + n * W68 + kp2 * 8) = v;
    }
    __syncthreads();

    float acc[2][4][4];
    #pragma unroll
    for (int s = 0; s < 2; s++)
        #pragma unroll
        for (int j = 0; j < 4; j++)
            { acc[s][j][0]=0.f; acc[s][j][1]=0.f; acc[s][j][2]=0.f; acc[s][j][3]=0.f; }

    #pragma unroll
    for (int k0 = 0; k0 < 8; k0++) {
        int kb = k0 * 32 + cb;
        uint32_t a[2][4];
        ldA_s(a[0], sA + (p * 32 + r4) * W68 + kb, W68);
        ldA_s(a[1], sA + (p * 32 + 16 + r4) * W68 + kb, W68);
        #pragma unroll
        for (int j = 0; j < 4; j++) {
            uint32_t b[2];
            ldB(b, sW + (q * 32 + j * 8 + r4) * W68 + kb);
            mma_tf32(acc[0][j], a[0], b);
            mma_tf32(acc[1][j], a[1], b);
        }
    }

    #pragma unroll
    for (int s = 0; s < 2; s++) {
        #pragma unroll
        for (int rh = 0; rh < 2; rh++) {
            int gn = base + p * 32 + s * 16 + rh * 8 + r4;
            if (gn < NN) {
                #pragma unroll
                for (int j = 0; j < 4; j++) {
                    int c0 = q * 32 + j * 8 + c2;
                    float2 o;
                    o.x = acc[s][j][rh * 2]     + __ldg(b1a + c0);
                    o.y = acc[s][j][rh * 2 + 1] + __ldg(b1a + c0 + 1);
                    *(float2*)(g_P + (size_t)gn * 128 + c0) = o;
                }
            }
        }
    }
}

// ============================ EDGE KERNEL (fp16) =============================
// 64-edge tiles, 256 threads, 2 CTA/SM.  W1aR fp16 fragments in registers.
// h & eattr fp16 in sXH (272B rows); P fp32 via cp.async overlapped w/ GEMM1.
#define EO_COL 0                      // int [2][64]
#define EO_ROW 512                    // int [2][64]
#define EO_B1B 1024                   // 64 f
#define EO_XH  1280                   // 64 x 272 (fp16)
#define EO_WB  (EO_XH + 64 * HB)      // 64 x 272 (fp16 W1b)
#define EO_P   (EO_WB + 64 * HB)      // 64 x 528 (fp32 P)
#define SMEM_EDGE (EO_P + 64 * W132)  // 69888 B

__global__ __launch_bounds__(256, 2)
void edge_kernel(const int* __restrict__ eidx, const float* __restrict__ eattr,
                 const float* __restrict__ W1a, const float* __restrict__ W1b,
                 const float* __restrict__ b1b)
{
    extern __shared__ char sm[];
    int*   sCol = (int*)(sm + EO_COL);
    int*   sRow = (int*)(sm + EO_ROW);
    float* sb1b = (float*)(sm + EO_B1B);
    char* sXH = sm + EO_XH;
    char* sWb = sm + EO_WB;
    char* sP  = sm + EO_P;

    const int tid = threadIdx.x, lane = tid & 31, w = tid >> 5;
    const int p = w & 1, q = w >> 1;
    const int r4 = lane >> 2, t3 = lane & 3;
    const int cb = t3 * 4, c2 = t3 * 2;

    // stage W1b (fp16) into smem: row n, 128 halves
    for (int idx = tid; idx < 64 * 64; idx += 256) {
        int r = idx >> 6, kp2 = idx & 63;
        float2 v = *(const float2*)(W1b + r * 128 + kp2 * 2);
        *(uint32_t*)(sWb + r * HB + kp2 * 4) = f2h2(v.x, v.y);
    }
    if (tid < 64) sb1b[tid] = b1b[tid];

    // W1aR (cols 64..127) fp16 fragments -> registers (m16n8k16 B layout)
    uint32_t bfrag[4][4][2];
    #pragma unroll
    for (int k0 = 0; k0 < 4; k0++) {
        #pragma unroll
        for (int j = 0; j < 4; j++) {
            int n0 = q * 32 + j * 8 + r4;
            const float* wp = W1a + n0 * 128 + 64 + k0 * 16 + t3 * 2;
            bfrag[k0][j][0] = f2h2(__ldg(wp),     __ldg(wp + 1));
            bfrag[k0][j][1] = f2h2(__ldg(wp + 8), __ldg(wp + 9));
        }
    }

    const int* rowI = eidx;        // int32 (jax x64 disabled)
    const int* colI = eidx + NE;
    const int step = gridDim.x;
    const int ntiles = NE / 64;

    int t = blockIdx.x;
    if (tid < 64 && t < ntiles) {
        sRow[tid] = rowI[t * 64 + tid];
        sCol[tid] = colI[t * 64 + tid];
    }
    __syncthreads();

    int buf = 0;
    for (; t < ntiles; t += step) {
        const int base = t * 64;
        const int* curCol = sCol + buf * 64;
        const int* curRow = sRow + buf * 64;

        // ---- cp.async: P[col[e]] rows (fp32, coalesced), overlaps GEMM1 ----
        #pragma unroll
        for (int i = 0; i < 8; i++) {
            int idx = i * 256 + tid;
            int e = idx >> 5, o16 = (idx & 31) * 16;
            cp_async16(sP + e * W132 + o16,
                       (const char*)(g_P + (size_t)curCol[e] * 128) + o16);
        }
        CP_COMMIT();

        // ---- stage eattr tile as fp16 (coalesced LDG + cvt + STS) ----
        #pragma unroll
        for (int i = 0; i < 8; i++) {
            int idx = i * 256 + tid;
            int e = idx >> 5, kp2 = idx & 31;
            float2 v = *(const float2*)(eattr + (size_t)(base + e) * 64 + kp2 * 2);
            *(uint32_t*)(sXH + e * HB + kp2 * 4) = f2h2(v.x, v.y);
        }

        // prefetch next tile's indices (overlaps GEMM1)
        int nr = 0, nc = 0;
        int tn = t + step;
        if (tid < 64 && tn < ntiles) {
            nr = rowI[tn * 64 + tid];
            nc = colI[tn * 64 + tid];
        }
        __syncthreads();            // sXH ready

        // ---- GEMM1: eattr @ W1aR^T (K=64 -> 4 k16 steps; B in regs) ----
        float acc[2][4][4];
        #pragma unroll
        for (int s = 0; s < 2; s++)
            #pragma unroll
            for (int j = 0; j < 4; j++)
                { acc[s][j][0]=0.f; acc[s][j][1]=0.f; acc[s][j][2]=0.f; acc[s][j][3]=0.f; }

        #pragma unroll
        for (int k0 = 0; k0 < 4; k0++) {
            int kb = k0 * 32 + cb;
            uint32_t a[2][4];
            ldA_s(a[0], sXH + (p * 32 + r4) * HB + kb, HB);
            ldA_s(a[1], sXH + (p * 32 + 16 + r4) * HB + kb, HB);
            #pragma unroll
            for (int j = 0; j < 4; j++) {
                mma_f16(acc[0][j], a[0], bfrag[k0][j]);
                mma_f16(acc[1][j], a[1], bfrag[k0][j]);
            }
        }
        CP_WAIT0();                 // P landed (overlapped with GEMM1)
        __syncthreads();            // sXH free + sP visible

        // ---- epi1: h = fp16(relu(acc + sP)) -> sXH ----
        #pragma unroll
        for (int s = 0; s < 2; s++) {
            int r0 = p * 32 + s * 16 + r4;
            #pragma unroll
            for (int j = 0; j < 4; j++) {
                int c0 = q * 32 + j * 8 + c2;
                float2 pa = *(const float2*)(sP + r0 * W132 + c0 * 4);
                float2 pb = *(const float2*)(sP + (r0 + 8) * W132 + c0 * 4);
                *(uint32_t*)(sXH + r0 * HB + c0 * 2) =
                    f2h2(fmaxf(acc[s][j][0] + pa.x, 0.f), fmaxf(acc[s][j][1] + pa.y, 0.f));
                *(uint32_t*)(sXH + (r0 + 8) * HB + c0 * 2) =
                    f2h2(fmaxf(acc[s][j][2] + pb.x, 0.f), fmaxf(acc[s][j][3] + pb.y, 0.f));
            }
        }
        __syncthreads();

        // ---- GEMM2: h @ W1b^T (K=128 -> 8 k16 steps, N=64) ----
        float acc2[2][2][4];
        #pragma unroll
        for (int s = 0; s < 2; s++)
            #pragma unroll
            for (int j = 0; j < 2; j++)
                { acc2[s][j][0]=0.f; acc2[s][j][1]=0.f; acc2[s][j][2]=0.f; acc2[s][j][3]=0.f; }

        #pragma unroll
        for (int k0 = 0; k0 < 8; k0++) {
            int kb = k0 * 32 + cb;
            uint32_t a[2][4];
            ldA_s(a[0], sXH + (p * 32 + r4) * HB + kb, HB);
            ldA_s(a[1], sXH + (p * 32 + 16 + r4) * HB + kb, HB);
            #pragma unroll
            for (int j = 0; j < 2; j++) {
                uint32_t b[2];
                ldB(b, sWb + (q * 16 + j * 8 + r4) * HB + kb);
                mma_f16(acc2[0][j], a[0], b);
                mma_f16(acc2[1][j], a[1], b);
            }
        }

        // ---- epi2: +b1b, scatter-add, count (fire-and-forget) ----
        #pragma unroll
        for (int s = 0; s < 2; s++) {
            #pragma unroll
            for (int rh = 0; rh < 2; rh++) {
                int e = p * 32 + s * 16 + rh * 8 + r4;
                int r = curRow[e];
                if (q == 0 && t3 == 0) atomicAdd(&g_cnt[r], 1.0f);
                float* dst = g_sums + (size_t)r * 64;
                #pragma unroll
                for (int j = 0; j < 2; j++) {
                    int c0 = q * 16 + j * 8 + c2;
                    REDV2(dst + c0,
                          acc2[s][j][rh * 2]     + sb1b[c0],
                          acc2[s][j][rh * 2 + 1] + sb1b[c0 + 1]);
                }
            }
        }

        if (tid < 64) {
            sRow[(buf ^ 1) * 64 + tid] = nr;
            sCol[(buf ^ 1) * 64 + tid] = nc;
        }
        buf ^= 1;
        __syncthreads();
    }
}

// ============================== NODE KERNEL (fp16) ===========================
// 64-node tiles, 1024 threads (32 warps), 1 CTA/SM.
#define NO_A   1280                       // 64 x 272 fp16  [src|agg]
#define NO_H   (NO_A + 64 * HB)           // 64 x 272 fp16
#define NO_WA  (NO_H + 64 * HB)           // 128 x 272 fp16
#define NO_WB  (NO_WA + 128 * HB)         // 64 x 272 fp16
#define NO_WR  (NO_WB + 64 * HB)          // 64 x 272 fp16
#define SMEM_NODE (NO_WR + 64 * HB)       // 105728 B

__device__ __forceinline__ void stage_w_h(const float* __restrict__ W, char* dst, int R,
                                          int swap, int nthr) {
    for (int idx = threadIdx.x; idx < R * 64; idx += nthr) {
        int r = idx >> 6, kp2 = idx & 63;
        float2 v = *(const float2*)(W + r * 128 + kp2 * 2);
        int kd = swap ? (kp2 ^ 32) : kp2;
        *(uint32_t*)(dst + r * HB + kd * 4) = f2h2(v.x, v.y);
    }
}

__global__ __launch_bounds__(1024, 1)
void node_kernel(const float* __restrict__ src,
                 const float* __restrict__ W2a, const float* __restrict__ b2a,
                 const float* __restrict__ W2b, const float* __restrict__ b2b,
                 const float* __restrict__ Wr,  const float* __restrict__ br,
                 float* __restrict__ out)
{
    extern __shared__ char sm[];
    float* sb2a = (float*)sm;
    float* sb2b = (float*)(sm + 512);
    float* sbr  = (float*)(sm + 768);
    float* sInv = (float*)(sm + 1024);
    char* sA  = sm + NO_A;
    char* sH  = sm + NO_H;
    char* sWa = sm + NO_WA;
    char* sWb = sm + NO_WB;
    char* sWr = sm + NO_WR;

    const int tid = threadIdx.x, lane = tid & 31, w = tid >> 5;
    stage_w_h(W2a, sWa, 128, 0, 1024);
    stage_w_h(W2b, sWb, 64, 0, 1024);
    stage_w_h(Wr,  sWr, 64, 1, 1024);   // k-halves swapped: A=[src|z] vs concat(z,src)
    if (tid < 128) sb2a[tid] = b2a[tid];
    if (tid < 64)  sb2b[tid] = b2b[tid];
    if (tid < 64)  sbr[tid]  = br[tid];

    const int p = w & 3, jj = w >> 2;   // p: 16-row strip (4), jj: col group (8)
    const int r4 = lane >> 2, t3 = lane & 3;
    const int cb = t3 * 4, c2 = t3 * 2;
    const int m0 = p * 16;

    const int ntiles = (NN + 63) / 64;
    for (int t = blockIdx.x; t < ntiles; t += gridDim.x) {
        const int base = t * 64;
        __syncthreads();
        if (tid < 64) {
            int gn = base + tid;
            float c = (gn < NN) ? g_cnt[gn] : 1.0f;
            sInv[tid] = 1.0f / fmaxf(c, 1.0f);
        }
        __syncthreads();

        // ---- stage A = [src | agg] (fp16) ----
        #pragma unroll
        for (int i = 0; i < 4; i++) {
            int idx = i * 1024 + tid;
            int n = idx >> 6, kp2 = idx & 63;
            int gn = base + n;
            float2 v = make_float2(0.f, 0.f);
            if (gn < NN) {
                if (kp2 < 32) v = *(const float2*)(src + (size_t)gn * 64 + kp2 * 2);
                else {
                    float2 s2 = *(const float2*)(g_sums + (size_t)gn * 64 + (kp2 - 32) * 2);
                    float iv = sInv[n];
                    v = make_float2(s2.x * iv, s2.y * iv);
                }
            }
            *(uint32_t*)(sA + n * HB + kp2 * 4) = f2h2(v.x, v.y);
        }
        __syncthreads();

        // ---- GEMM1: h = A @ W2a^T (K=128 -> 8 k16 steps, 2 n8-tiles/warp) ----
        float acc[2][4];
        #pragma unroll
        for (int j = 0; j < 2; j++) { acc[j][0]=0.f; acc[j][1]=0.f; acc[j][2]=0.f; acc[j][3]=0.f; }
        #pragma unroll
        for (int k0 = 0; k0 < 8; k0++) {
            int kb = k0 * 32 + cb;
            uint32_t a[4];
            ldA_s(a, sA + (m0 + r4) * HB + kb, HB);
            #pragma unroll
            for (int j = 0; j < 2; j++) {
                uint32_t b[2];
                ldB(b, sWa + (jj * 16 + j * 8 + r4) * HB + kb);
                mma_f16(acc[j], a, b);
            }
        }
        #pragma unroll
        for (int j = 0; j < 2; j++) {
            int c0 = jj * 16 + j * 8 + c2;
            float bx = sb2a[c0], by = sb2a[c0 + 1];
            *(uint32_t*)(sH + (m0 + r4) * HB + c0 * 2) =
                f2h2(fmaxf(acc[j][0] + bx, 0.f), fmaxf(acc[j][1] + by, 0.f));
            *(uint32_t*)(sH + (m0 + 8 + r4) * HB + c0 * 2) =
                f2h2(fmaxf(acc[j][2] + bx, 0.f), fmaxf(acc[j][3] + by, 0.f));
        }
        __syncthreads();

        // ---- GEMM2: z = h @ W2b^T (1 n8-tile/warp) ----
        float acc2[4];
        acc2[0]=0.f; acc2[1]=0.f; acc2[2]=0.f; acc2[3]=0.f;
        #pragma unroll
        for (int k0 = 0; k0 < 8; k0++) {
            int kb = k0 * 32 + cb;
            uint32_t a[4];
            ldA_s(a, sH + (m0 + r4) * HB + kb, HB);
            uint32_t b[2];
            ldB(b, sWb + (jj * 8 + r4) * HB + kb);
            mma_f16(acc2, a, b);
        }
        {
            int c0 = jj * 8 + c2;
            float bx = sb2b[c0], by = sb2b[c0 + 1];
            *(uint32_t*)(sA + (m0 + r4) * HB + (64 + c0) * 2) =
                f2h2(acc2[0] + bx, acc2[1] + by);
            *(uint32_t*)(sA + (m0 + 8 + r4) * HB + (64 + c0) * 2) =
                f2h2(acc2[2] + bx, acc2[3] + by);
        }
        __syncthreads();

        // ---- GEMM3: out = [src|z] @ WrPerm^T ----
        float acc3[4];
        acc3[0]=0.f; acc3[1]=0.f; acc3[2]=0.f; acc3[3]=0.f;
        #pragma unroll
        for (int k0 = 0; k0 < 8; k0++) {
            int kb = k0 * 32 + cb;
            uint32_t a[4];
            ldA_s(a, sA + (m0 + r4) * HB + kb, HB);
            uint32_t b[2];
            ldB(b, sWr + (jj * 8 + r4) * HB + kb);
            mma_f16(acc3, a, b);
        }
        #pragma unroll
        for (int rh = 0; rh < 2; rh++) {
            int gn = base + m0 + rh * 8 + r4;
            if (gn < NN) {
                int c0 = jj * 8 + c2;
                float2 o = make_float2(acc3[rh * 2] + sbr[c0],
                                       acc3[rh * 2 + 1] + sbr[c0 + 1]);
                *(float2*)(out + (size_t)gn * 64 + c0) = o;
            }
        }
    }
}

// ---------------------------------------------------------------------------
extern "C" void kernel_launch(void* const* d_in, const int* in_sizes, int n_in,
                              void* d_out, int out_size) {
    const float* src   = (const float*)d_in[0];
    const int*   eidx  = (const int*)d_in[1];
    const float* eattr = (const float*)d_in[2];
    const float* W1a = (const float*)d_in[5];
    const float* b1a = (const float*)d_in[6];
    const float* W1b = (const float*)d_in[7];
    const float* b1b = (const float*)d_in[8];
    const float* W2a = (const float*)d_in[9];
    const float* b2a = (const float*)d_in[10];
    const float* W2b = (const float*)d_in[11];
    const float* b2b = (const float*)d_in[12];
    const float* Wr  = (const float*)d_in[13];
    const float* br  = (const float*)d_in[14];
    float* out = (float*)d_out;

    cudaFuncSetAttribute(p_kernel,    cudaFuncAttributeMaxDynamicSharedMemorySize, SMEM_P);
    cudaFuncSetAttribute(edge_kernel, cudaFuncAttributeMaxDynamicSharedMemorySize, SMEM_EDGE);
    cudaFuncSetAttribute(node_kernel, cudaFuncAttributeMaxDynamicSharedMemorySize, SMEM_NODE);

    zero_kernel<<<(NN * 16 + 255) / 256, 256>>>();
    p_kernel<<<(NN + 63) / 64, 256, SMEM_P>>>(src, W1a, b1a);
    edge_kernel<<<296, 256, SMEM_EDGE>>>(eidx, eattr, W1a, W1b, b1b);
    node_kernel<<<148, 1024, SMEM_NODE>>>(src, W2a, b2a, W2b, b2b, Wr, br, out);
}

// round 14
// speedup vs baseline: 1.7788x; 1.1361x over previous
#include <cuda_runtime.h>
#include <cuda_fp16.h>
#include <cstdint>

#define NN 50000
#define NE 800000

__device__ __align__(16) float g_sums[NN * 64];
__device__ __align__(16) float g_cnt[NN];
__device__ __align__(16) __half g_P[NN * 128];   // P = src @ W1aL^T + b1a (fp16)

__global__ void zero_kernel() {
    int i = blockIdx.x * blockDim.x + threadIdx.x;
    float4 z = make_float4(0.f, 0.f, 0.f, 0.f);
    if (i < NN * 16) ((float4*)g_sums)[i] = z;
    if (i < NN / 4 + 1 && i * 4 + 3 < NN) ((float4*)g_cnt)[i] = z;
    if (i < 4) g_cnt[NN - 1 - i] = 0.f;
}

__device__ __forceinline__ float to_tf32(float x) {
    float y;
    asm("cvt.rna.tf32.f32 %0, %1;" : "=f"(y) : "f"(x));
    return y;
}
__device__ __forceinline__ uint32_t f2h2(float x, float y) {
    __half2 h = __floats2half2_rn(x, y);
    return *reinterpret_cast<uint32_t*>(&h);
}
__device__ __forceinline__ float2 h22f2(uint32_t u) {
    __half2 h = *reinterpret_cast<__half2*>(&u);
    return __half22float2(h);
}

__device__ __forceinline__ void mma_tf32(float d[4], const uint32_t a[4], const uint32_t b[2]) {
    asm volatile(
        "mma.sync.aligned.m16n8k8.row.col.f32.tf32.tf32.f32 "
        "{%0,%1,%2,%3}, {%4,%5,%6,%7}, {%8,%9}, {%0,%1,%2,%3};"
        : "+f"(d[0]), "+f"(d[1]), "+f"(d[2]), "+f"(d[3])
        : "r"(a[0]), "r"(a[1]), "r"(a[2]), "r"(a[3]), "r"(b[0]), "r"(b[1]));
}
__device__ __forceinline__ void mma_f16(float d[4], const uint32_t a[4], const uint32_t b[2]) {
    asm volatile(
        "mma.sync.aligned.m16n8k16.row.col.f32.f16.f16.f32 "
        "{%0,%1,%2,%3}, {%4,%5,%6,%7}, {%8,%9}, {%0,%1,%2,%3};"
        : "+f"(d[0]), "+f"(d[1]), "+f"(d[2]), "+f"(d[3])
        : "r"(a[0]), "r"(a[1]), "r"(a[2]), "r"(a[3]), "r"(b[0]), "r"(b[1]));
}

__device__ __forceinline__ void ldA_s(uint32_t a[4], const char* p, int stride) {
    a[0] = *(const uint32_t*)p;
    a[1] = *(const uint32_t*)(p + 8 * stride);
    a[2] = *(const uint32_t*)(p + 16);
    a[3] = *(const uint32_t*)(p + 8 * stride + 16);
}
__device__ __forceinline__ void ldB(uint32_t b[2], const char* p) {
    b[0] = *(const uint32_t*)p;
    b[1] = *(const uint32_t*)(p + 16);
}

#define REDV2(ptr, x0, x1) \
    asm volatile("red.global.add.v2.f32 [%0], {%1,%2};" :: "l"(ptr), "f"(x0), "f"(x1) : "memory")

__device__ __forceinline__ void cp_async16(void* dst_smem, const void* src_g) {
    uint32_t d;
    asm("{ .reg .u64 t; cvta.to.shared.u64 t, %1; cvt.u32.u64 %0, t; }" : "=r"(d) : "l"(dst_smem));
    asm volatile("cp.async.cg.shared.global [%0], [%1], 16;" :: "r"(d), "l"(src_g) : "memory");
}
#define CP_COMMIT() asm volatile("cp.async.commit_group;" ::: "memory")
#define CP_WAIT0()  asm volatile("cp.async.wait_group 0;" ::: "memory")

#define W68  272     // tf32 rows: 68 floats
#define HB   272     // fp16 rows: 136 halves (conflict-free, proven)

// ============================ P kernel (tf32 compute, fp16 out) ==============
#define PO_A 0
#define PO_W 17408
#define SMEM_P (PO_W + 34816)

__global__ __launch_bounds__(256, 2)
void p_kernel(const float* __restrict__ src, const float* __restrict__ W1a,
              const float* __restrict__ b1a)
{
    extern __shared__ char sm[];
    char* sA = sm + PO_A;
    char* sW = sm + PO_W;
    const int tid = threadIdx.x, lane = tid & 31, w = tid >> 5;
    const int p = w & 1, q = w >> 1;
    const int r4 = lane >> 2, cb = (lane & 3) * 4, c2 = (lane & 3) * 2;

    for (int idx = tid; idx < 128 * 32; idx += 256) {
        int r = idx >> 5, kp2 = idx & 31;
        float2 v = *(const float2*)(W1a + r * 128 + kp2 * 2);
        v.x = to_tf32(v.x); v.y = to_tf32(v.y);
        *(float2*)(sW + r * W68 + kp2 * 8) = v;
    }

    const int base = blockIdx.x * 64;
    for (int idx = tid; idx < 64 * 32; idx += 256) {
        int n = idx >> 5, kp2 = idx & 31;
        int gn = base + n;
        float2 v = make_float2(0.f, 0.f);
        if (gn < NN) v = *(const float2*)(src + (size_t)gn * 64 + kp2 * 2);
        v.x = to_tf32(v.x); v.y = to_tf32(v.y);
        *(float2*)(sA + n * W68 + kp2 * 8) = v;
    }
    __syncthreads();

    float acc[2][4][4];
    #pragma unroll
    for (int s = 0; s < 2; s++)
        #pragma unroll
        for (int j = 0; j < 4; j++)
            { acc[s][j][0]=0.f; acc[s][j][1]=0.f; acc[s][j][2]=0.f; acc[s][j][3]=0.f; }

    #pragma unroll
    for (int k0 = 0; k0 < 8; k0++) {
        int kb = k0 * 32 + cb;
        uint32_t a[2][4];
        ldA_s(a[0], sA + (p * 32 + r4) * W68 + kb, W68);
        ldA_s(a[1], sA + (p * 32 + 16 + r4) * W68 + kb, W68);
        #pragma unroll
        for (int j = 0; j < 4; j++) {
            uint32_t b[2];
            ldB(b, sW + (q * 32 + j * 8 + r4) * W68 + kb);
            mma_tf32(acc[0][j], a[0], b);
            mma_tf32(acc[1][j], a[1], b);
        }
    }

    #pragma unroll
    for (int s = 0; s < 2; s++) {
        #pragma unroll
        for (int rh = 0; rh < 2; rh++) {
            int gn = base + p * 32 + s * 16 + rh * 8 + r4;
            if (gn < NN) {
                #pragma unroll
                for (int j = 0; j < 4; j++) {
                    int c0 = q * 32 + j * 8 + c2;
                    float ox = acc[s][j][rh * 2]     + __ldg(b1a + c0);
                    float oy = acc[s][j][rh * 2 + 1] + __ldg(b1a + c0 + 1);
                    *(uint32_t*)(g_P + (size_t)gn * 128 + c0) = f2h2(ox, oy);
                }
            }
        }
    }
}

// ============================ EDGE KERNEL (fp16) =============================
// 64-edge tiles, 256 threads, 2 CTA/SM.  W1aR fp16 fragments in registers.
// P (fp16) via cp.async overlapped w/ GEMM1.  smem 53.5 KB.
#define EO_COL 0                      // int [2][64]
#define EO_ROW 512                    // int [2][64]
#define EO_B1B 1024                   // 64 f
#define EO_XH  1280                   // 64 x 272 (fp16)
#define EO_WB  (EO_XH + 64 * HB)      // 64 x 272 (fp16 W1b)
#define EO_P   (EO_WB + 64 * HB)      // 64 x 272 (fp16 P)
#define SMEM_EDGE (EO_P + 64 * HB)    // 53504 B

__global__ __launch_bounds__(256, 2)
void edge_kernel(const int* __restrict__ eidx, const float* __restrict__ eattr,
                 const float* __restrict__ W1a, const float* __restrict__ W1b,
                 const float* __restrict__ b1b)
{
    extern __shared__ char sm[];
    int*   sCol = (int*)(sm + EO_COL);
    int*   sRow = (int*)(sm + EO_ROW);
    float* sb1b = (float*)(sm + EO_B1B);
    char* sXH = sm + EO_XH;
    char* sWb = sm + EO_WB;
    char* sP  = sm + EO_P;

    const int tid = threadIdx.x, lane = tid & 31, w = tid >> 5;
    const int p = w & 1, q = w >> 1;
    const int r4 = lane >> 2, t3 = lane & 3;
    const int cb = t3 * 4, c2 = t3 * 2;

    // stage W1b (fp16) into smem
    for (int idx = tid; idx < 64 * 64; idx += 256) {
        int r = idx >> 6, kp2 = idx & 63;
        float2 v = *(const float2*)(W1b + r * 128 + kp2 * 2);
        *(uint32_t*)(sWb + r * HB + kp2 * 4) = f2h2(v.x, v.y);
    }
    if (tid < 64) sb1b[tid] = b1b[tid];

    // W1aR (cols 64..127) fp16 fragments -> registers
    uint32_t bfrag[4][4][2];
    #pragma unroll
    for (int k0 = 0; k0 < 4; k0++) {
        #pragma unroll
        for (int j = 0; j < 4; j++) {
            int n0 = q * 32 + j * 8 + r4;
            const float* wp = W1a + n0 * 128 + 64 + k0 * 16 + t3 * 2;
            bfrag[k0][j][0] = f2h2(__ldg(wp),     __ldg(wp + 1));
            bfrag[k0][j][1] = f2h2(__ldg(wp + 8), __ldg(wp + 9));
        }
    }

    const int* rowI = eidx;        // int32 (jax x64 disabled)
    const int* colI = eidx + NE;
    const int step = gridDim.x;
    const int ntiles = NE / 64;

    int t = blockIdx.x;
    if (tid < 64 && t < ntiles) {
        sRow[tid] = rowI[t * 64 + tid];
        sCol[tid] = colI[t * 64 + tid];
    }
    __syncthreads();

    int buf = 0;
    for (; t < ntiles; t += step) {
        const int base = t * 64;
        const int* curCol = sCol + buf * 64;
        const int* curRow = sRow + buf * 64;

        // ---- cp.async: P[col[e]] rows (fp16, 256B/row), overlaps GEMM1 ----
        #pragma unroll
        for (int i = 0; i < 4; i++) {
            int idx = i * 256 + tid;            // 1024 x 16B
            int e = idx >> 4, o16 = (idx & 15) * 16;
            cp_async16(sP + e * HB + o16,
                       (const char*)(g_P + (size_t)curCol[e] * 128) + o16);
        }
        CP_COMMIT();

        // ---- stage eattr tile as fp16 ----
        #pragma unroll
        for (int i = 0; i < 8; i++) {
            int idx = i * 256 + tid;
            int e = idx >> 5, kp2 = idx & 31;
            float2 v = *(const float2*)(eattr + (size_t)(base + e) * 64 + kp2 * 2);
            *(uint32_t*)(sXH + e * HB + kp2 * 4) = f2h2(v.x, v.y);
        }

        // prefetch next tile's indices (overlaps GEMM1)
        int nr = 0, nc = 0;
        int tn = t + step;
        if (tid < 64 && tn < ntiles) {
            nr = rowI[tn * 64 + tid];
            nc = colI[tn * 64 + tid];
        }
        __syncthreads();            // sXH ready

        // ---- GEMM1: eattr @ W1aR^T (K=64 -> 4 k16 steps; B in regs) ----
        float acc[2][4][4];
        #pragma unroll
        for (int s = 0; s < 2; s++)
            #pragma unroll
            for (int j = 0; j < 4; j++)
                { acc[s][j][0]=0.f; acc[s][j][1]=0.f; acc[s][j][2]=0.f; acc[s][j][3]=0.f; }

        #pragma unroll
        for (int k0 = 0; k0 < 4; k0++) {
            int kb = k0 * 32 + cb;
            uint32_t a[2][4];
            ldA_s(a[0], sXH + (p * 32 + r4) * HB + kb, HB);
            ldA_s(a[1], sXH + (p * 32 + 16 + r4) * HB + kb, HB);
            #pragma unroll
            for (int j = 0; j < 4; j++) {
                mma_f16(acc[0][j], a[0], bfrag[k0][j]);
                mma_f16(acc[1][j], a[1], bfrag[k0][j]);
            }
        }
        CP_WAIT0();                 // P landed (overlapped with GEMM1)
        __syncthreads();            // sXH free + sP visible

        // ---- epi1: h = fp16(relu(acc + sP)) -> sXH ----
        #pragma unroll
        for (int s = 0; s < 2; s++) {
            int r0 = p * 32 + s * 16 + r4;
            #pragma unroll
            for (int j = 0; j < 4; j++) {
                int c0 = q * 32 + j * 8 + c2;
                float2 pa = h22f2(*(const uint32_t*)(sP + r0 * HB + c0 * 2));
                float2 pb = h22f2(*(const uint32_t*)(sP + (r0 + 8) * HB + c0 * 2));
                *(uint32_t*)(sXH + r0 * HB + c0 * 2) =
                    f2h2(fmaxf(acc[s][j][0] + pa.x, 0.f), fmaxf(acc[s][j][1] + pa.y, 0.f));
                *(uint32_t*)(sXH + (r0 + 8) * HB + c0 * 2) =
                    f2h2(fmaxf(acc[s][j][2] + pb.x, 0.f), fmaxf(acc[s][j][3] + pb.y, 0.f));
            }
        }
        __syncthreads();

        // ---- GEMM2: h @ W1b^T (K=128 -> 8 k16 steps, N=64) ----
        float acc2[2][2][4];
        #pragma unroll
        for (int s = 0; s < 2; s++)
            #pragma unroll
            for (int j = 0; j < 2; j++)
                { acc2[s][j][0]=0.f; acc2[s][j][1]=0.f; acc2[s][j][2]=0.f; acc2[s][j][3]=0.f; }

        #pragma unroll
        for (int k0 = 0; k0 < 8; k0++) {
            int kb = k0 * 32 + cb;
            uint32_t a[2][4];
            ldA_s(a[0], sXH + (p * 32 + r4) * HB + kb, HB);
            ldA_s(a[1], sXH + (p * 32 + 16 + r4) * HB + kb, HB);
            #pragma unroll
            for (int j = 0; j < 2; j++) {
                uint32_t b[2];
                ldB(b, sWb + (q * 16 + j * 8 + r4) * HB + kb);
                mma_f16(acc2[0][j], a[0], b);
                mma_f16(acc2[1][j], a[1], b);
            }
        }

        // ---- epi2: +b1b, scatter-add, count (fire-and-forget) ----
        #pragma unroll
        for (int s = 0; s < 2; s++) {
            #pragma unroll
            for (int rh = 0; rh < 2; rh++) {
                int e = p * 32 + s * 16 + rh * 8 + r4;
                int r = curRow[e];
                if (q == 0 && t3 == 0) atomicAdd(&g_cnt[r], 1.0f);
                float* dst = g_sums + (size_t)r * 64;
                #pragma unroll
                for (int j = 0; j < 2; j++) {
                    int c0 = q * 16 + j * 8 + c2;
                    REDV2(dst + c0,
                          acc2[s][j][rh * 2]     + sb1b[c0],
                          acc2[s][j][rh * 2 + 1] + sb1b[c0 + 1]);
                }
            }
        }

        if (tid < 64) {
            sRow[(buf ^ 1) * 64 + tid] = nr;
            sCol[(buf ^ 1) * 64 + tid] = nc;
        }
        buf ^= 1;
        __syncthreads();
    }
}

// ============================== NODE KERNEL (fp16) ===========================
// 128-node tiles, 1024 threads (32 warps), 1 CTA/SM.
#define NO_A   1536                       // 128 x 272 fp16  [src|agg]
#define NO_H   (NO_A + 128 * HB)          // 128 x 272 fp16
#define NO_WA  (NO_H + 128 * HB)          // 128 x 272 fp16
#define NO_WB  (NO_WA + 128 * HB)         // 64 x 272 fp16
#define NO_WR  (NO_WB + 64 * HB)          // 64 x 272 fp16
#define SMEM_NODE (NO_WR + 64 * HB)       // 140800 B

__device__ __forceinline__ void stage_w_h(const float* __restrict__ W, char* dst, int R,
                                          int swap, int nthr) {
    for (int idx = threadIdx.x; idx < R * 64; idx += nthr) {
        int r = idx >> 6, kp2 = idx & 63;
        float2 v = *(const float2*)(W + r * 128 + kp2 * 2);
        int kd = swap ? (kp2 ^ 32) : kp2;
        *(uint32_t*)(dst + r * HB + kd * 4) = f2h2(v.x, v.y);
    }
}

__global__ __launch_bounds__(1024, 1)
void node_kernel(const float* __restrict__ src,
                 const float* __restrict__ W2a, const float* __restrict__ b2a,
                 const float* __restrict__ W2b, const float* __restrict__ b2b,
                 const float* __restrict__ Wr,  const float* __restrict__ br,
                 float* __restrict__ out)
{
    extern __shared__ char sm[];
    float* sb2a = (float*)sm;
    float* sb2b = (float*)(sm + 512);
    float* sbr  = (float*)(sm + 768);
    float* sInv = (float*)(sm + 1024);     // 128 f
    char* sA  = sm + NO_A;
    char* sH  = sm + NO_H;
    char* sWa = sm + NO_WA;
    char* sWb = sm + NO_WB;
    char* sWr = sm + NO_WR;

    const int tid = threadIdx.x, lane = tid & 31, w = tid >> 5;
    stage_w_h(W2a, sWa, 128, 0, 1024);
    stage_w_h(W2b, sWb, 64, 0, 1024);
    stage_w_h(Wr,  sWr, 64, 1, 1024);   // k-halves swapped: A=[src|z] vs concat(z,src)
    if (tid < 128) sb2a[tid] = b2a[tid];
    if (tid < 64)  sb2b[tid] = b2b[tid];
    if (tid < 64)  sbr[tid]  = br[tid];

    const int p = w & 7, jj = w >> 3;   // p: 16-row strip (8), jj: col group (4)
    const int r4 = lane >> 2, t3 = lane & 3;
    const int cb = t3 * 4, c2 = t3 * 2;
    const int m0 = p * 16;

    const int ntiles = (NN + 127) / 128;   // 391
    for (int t = blockIdx.x; t < ntiles; t += gridDim.x) {
        const int base = t * 128;
        __syncthreads();
        if (tid < 128) {
            int gn = base + tid;
            float c = (gn < NN) ? g_cnt[gn] : 1.0f;
            sInv[tid] = 1.0f / fmaxf(c, 1.0f);
        }
        __syncthreads();

        // ---- stage A = [src | agg] (fp16), 128 rows ----
        #pragma unroll
        for (int i = 0; i < 4; i++) {
            int idx = i * 1024 + tid;
            int n = idx >> 5, kp2 = idx & 31;
            int gn = base + n;
            float2 vs = make_float2(0.f, 0.f), va = make_float2(0.f, 0.f);
            if (gn < NN) {
                vs = *(const float2*)(src + (size_t)gn * 64 + kp2 * 2);
                float2 s2 = *(const float2*)(g_sums + (size_t)gn * 64 + kp2 * 2);
                float iv = sInv[n];
                va = make_float2(s2.x * iv, s2.y * iv);
            }
            *(uint32_t*)(sA + n * HB + kp2 * 4)        = f2h2(vs.x, vs.y);
            *(uint32_t*)(sA + n * HB + (32 + kp2) * 4) = f2h2(va.x, va.y);
        }
        __syncthreads();

        // ---- GEMM1: h = A @ W2a^T (K=128 -> 8 k16, 4 n8-tiles/warp) ----
        float acc[4][4];
        #pragma unroll
        for (int j = 0; j < 4; j++) { acc[j][0]=0.f; acc[j][1]=0.f; acc[j][2]=0.f; acc[j][3]=0.f; }
        #pragma unroll
        for (int k0 = 0; k0 < 8; k0++) {
            int kb = k0 * 32 + cb;
            uint32_t a[4];
            ldA_s(a, sA + (m0 + r4) * HB + kb, HB);
            #pragma unroll
            for (int j = 0; j < 4; j++) {
                uint32_t b[2];
                ldB(b, sWa + (jj * 32 + j * 8 + r4) * HB + kb);
                mma_f16(acc[j], a, b);
            }
        }
        #pragma unroll
        for (int j = 0; j < 4; j++) {
            int c0 = jj * 32 + j * 8 + c2;
            float bx = sb2a[c0], by = sb2a[c0 + 1];
            *(uint32_t*)(sH + (m0 + r4) * HB + c0 * 2) =
                f2h2(fmaxf(acc[j][0] + bx, 0.f), fmaxf(acc[j][1] + by, 0.f));
            *(uint32_t*)(sH + (m0 + 8 + r4) * HB + c0 * 2) =
                f2h2(fmaxf(acc[j][2] + bx, 0.f), fmaxf(acc[j][3] + by, 0.f));
        }
        __syncthreads();

        // ---- GEMM2: z = h @ W2b^T (2 n8-tiles/warp) ----
        float acc2[2][4];
        #pragma unroll
        for (int j = 0; j < 2; j++) { acc2[j][0]=0.f; acc2[j][1]=0.f; acc2[j][2]=0.f; acc2[j][3]=0.f; }
        #pragma unroll
        for (int k0 = 0; k0 < 8; k0++) {
            int kb = k0 * 32 + cb;
            uint32_t a[4];
            ldA_s(a, sH + (m0 + r4) * HB + kb, HB);
            #pragma unroll
            for (int j = 0; j < 2; j++) {
                uint32_t b[2];
                ldB(b, sWb + (jj * 16 + j * 8 + r4) * HB + kb);
                mma_f16(acc2[j], a, b);
            }
        }
        #pragma unroll
        for (int j = 0; j < 2; j++) {
            int c0 = jj * 16 + j * 8 + c2;
            float bx = sb2b[c0], by = sb2b[c0 + 1];
            *(uint32_t*)(sA + (m0 + r4) * HB + (64 + c0) * 2) =
                f2h2(acc2[j][0] + bx, acc2[j][1] + by);
            *(uint32_t*)(sA + (m0 + 8 + r4) * HB + (64 + c0) * 2) =
                f2h2(acc2[j][2] + bx, acc2[j][3] + by);
        }
        __syncthreads();

        // ---- GEMM3: out = [src|z] @ WrPerm^T (2 n8-tiles/warp) ----
        float acc3[2][4];
        #pragma unroll
        for (int j = 0; j < 2; j++) { acc3[j][0]=0.f; acc3[j][1]=0.f; acc3[j][2]=0.f; acc3[j][3]=0.f; }
        #pragma unroll
        for (int k0 = 0; k0 < 8; k0++) {
            int kb = k0 * 32 + cb;
            uint32_t a[4];
            ldA_s(a, sA + (m0 + r4) * HB + kb, HB);
            #pragma unroll
            for (int j = 0; j < 2; j++) {
                uint32_t b[2];
                ldB(b, sWr + (jj * 16 + j * 8 + r4) * HB + kb);
                mma_f16(acc3[j], a, b);
            }
        }
        #pragma unroll
        for (int rh = 0; rh < 2; rh++) {
            int gn = base + m0 + rh * 8 + r4;
            if (gn < NN) {
                #pragma unroll
                for (int j = 0; j < 2; j++) {
                    int c0 = jj * 16 + j * 8 + c2;
                    float2 o = make_float2(acc3[j][rh * 2] + sbr[c0],
                                           acc3[j][rh * 2 + 1] + sbr[c0 + 1]);
                    *(float2*)(out + (size_t)gn * 64 + c0) = o;
                }
            }
        }
    }
}

// ---------------------------------------------------------------------------
extern "C" void kernel_launch(void* const* d_in, const int* in_sizes, int n_in,
                              void* d_out, int out_size) {
    const float* src   = (const float*)d_in[0];
    const int*   eidx  = (const int*)d_in[1];
    const float* eattr = (const float*)d_in[2];
    const float* W1a = (const float*)d_in[5];
    const float* b1a = (const float*)d_in[6];
    const float* W1b = (const float*)d_in[7];
    const float* b1b = (const float*)d_in[8];
    const float* W2a = (const float*)d_in[9];
    const float* b2a = (const float*)d_in[10];
    const float* W2b = (const float*)d_in[11];
    const float* b2b = (const float*)d_in[12];
    const float* Wr  = (const float*)d_in[13];
    const float* br  = (const float*)d_in[14];
    float* out = (float*)d_out;

    cudaFuncSetAttribute(p_kernel,    cudaFuncAttributeMaxDynamicSharedMemorySize, SMEM_P);
    cudaFuncSetAttribute(edge_kernel, cudaFuncAttributeMaxDynamicSharedMemorySize, SMEM_EDGE);
    cudaFuncSetAttribute(node_kernel, cudaFuncAttributeMaxDynamicSharedMemorySize, SMEM_NODE);

    zero_kernel<<<(NN * 16 + 255) / 256, 256>>>();
    p_kernel<<<(NN + 63) / 64, 256, SMEM_P>>>(src, W1a, b1a);
    edge_kernel<<<296, 256, SMEM_EDGE>>>(eidx, eattr, W1a, W1b, b1b);
    node_kernel<<<148, 1024, SMEM_NODE>>>(src, W2a, b2a, W2b, b2b, Wr, br, out);
}